// round 1
// baseline (speedup 1.0000x reference)
#include <cuda_runtime.h>
#include <cstdint>

typedef unsigned long long ull;

#define TILE_M   128
#define NTHREADS 256
#define LDE      514     // padded row length (floats) of e_s[d][k]

#define X2_ELEMS  (64*128)      // ull (f32x2) elements
#define RED_ELEMS (128*16)      // ull reduction scratch
#define E_ELEMS   (64*LDE)      // floats
#define SMEM_BYTES (X2_ELEMS*8 + RED_ELEMS*8 + E_ELEMS*4 + 128*4 + 512*4 + 128*4)

__device__ double g_loss_sum;

__global__ void vq_zero_kernel() { g_loss_sum = 0.0; }

__device__ __forceinline__ ull ffma2(ull a, ull b, ull c) {
    ull d;
    asm("fma.rn.f32x2 %0, %1, %2, %3;" : "=l"(d) : "l"(a), "l"(b), "l"(c));
    return d;
}
__device__ __forceinline__ float lo32(ull u) { return __uint_as_float((unsigned)u); }
__device__ __forceinline__ float hi32(ull u) { return __uint_as_float((unsigned)(u >> 32)); }
__device__ __forceinline__ ull   dup2(float v) {
    unsigned b = __float_as_uint(v);
    return ((ull)b << 32) | (ull)b;
}

__global__ __launch_bounds__(NTHREADS, 1)
void vq_main_kernel(const float* __restrict__ lat,
                    const float* __restrict__ emb,
                    float* __restrict__ out)
{
    extern __shared__ unsigned char smem_raw[];
    ull*   x2_s  = (ull*)smem_raw;                 // [d][r] duplicated x, 64*128
    ull*   red_s = x2_s + X2_ELEMS;                // [r][cg] packed (dist,k)
    float* e_s   = (float*)(red_s + RED_ELEMS);    // [d][k], ld=LDE
    float* t1_s  = e_s + E_ELEMS;                  // [128]
    float* t2_s  = t1_s + 128;                     // [512]
    int*   ind_s = (int*)(t2_s + 512);             // [128]

    const int tid = threadIdx.x;
    const int n0  = blockIdx.x * TILE_M;
    const int b   = n0 >> 12;                      // n0 / 4096 (H*W)
    const int p0  = n0 & 4095;
    const float* xg = lat + ((size_t)b << 18) + p0;    // b*64*4096 + p0

    // ---- load x tile (lane-duplicated f32x2), coalesced over r ----
    for (int i = tid; i < 64 * 128; i += NTHREADS) {
        int d = i >> 7, r = i & 127;
        float v = __ldg(&xg[(d << 12) + r]);       // lat[b][d][p0+r]
        x2_s[(d << 7) + r] = dup2(v);
    }
    // ---- load emb transposed into e_s[d*LDE + k], coalesced over d ----
    for (int i = tid; i < 512 * 64; i += NTHREADS) {
        int k = i >> 6, d = i & 63;
        e_s[d * LDE + k] = __ldg(&emb[i]);
    }
    __syncthreads();

    // ---- t1[r] = sequential fp32 sum of fl(x_d^2), d = 0..63 (replicates ref) ----
    if (tid < 128) {
        float acc = 0.0f;
        #pragma unroll 1
        for (int d = 0; d < 64; ++d) {
            float v = lo32(x2_s[(d << 7) + tid]);
            acc = __fadd_rn(acc, __fmul_rn(v, v));
        }
        t1_s[tid] = acc;
    }
    // ---- t2[k] = sequential fp32 sum of fl(e_d^2) ----
    for (int k = tid; k < 512; k += NTHREADS) {
        float acc = 0.0f;
        #pragma unroll 1
        for (int d = 0; d < 64; ++d) {
            float v = e_s[d * LDE + k];
            acc = __fadd_rn(acc, __fmul_rn(v, v));
        }
        t2_s[k] = acc;
    }
    __syncthreads();

    // ---- main GEMM + argmin: thread = (rg,cg), 8 rows x 16 codes per chunk ----
    const int rg = tid >> 4;      // 0..15 -> rows rg*8 .. rg*8+7
    const int cg = tid & 15;      // 0..15 -> codes kbase = chunk*256 + 2*cg + 32*j

    float t1r[8];
    ull   ukey[8];
    #pragma unroll
    for (int i = 0; i < 8; ++i) { t1r[i] = t1_s[rg * 8 + i]; ukey[i] = ~0ull; }

    #pragma unroll 1
    for (int chunk = 0; chunk < 2; ++chunk) {
        const int kbase = chunk * 256 + 2 * cg;
        ull acc[8][8];
        #pragma unroll
        for (int i = 0; i < 8; ++i)
            #pragma unroll
            for (int j = 0; j < 8; ++j)
                acc[i][j] = 0ull;

        const ull*   xp = x2_s + rg * 8;
        const float* ep = e_s + kbase;

        #pragma unroll 4
        for (int d = 0; d < 64; ++d) {
            ull xv[8], ev[8];
            #pragma unroll
            for (int i = 0; i < 8; ++i) xv[i] = xp[(d << 7) + i];
            #pragma unroll
            for (int j = 0; j < 8; ++j) ev[j] = *(const ull*)(ep + d * LDE + 32 * j);
            #pragma unroll
            for (int i = 0; i < 8; ++i)
                #pragma unroll
                for (int j = 0; j < 8; ++j)
                    acc[i][j] = ffma2(xv[i], ev[j], acc[i][j]);
        }

        // epilogue: dist = fl( fl(t1 + t2) - 2*m ), keep running packed min
        #pragma unroll
        for (int j = 0; j < 8; ++j) {
            const int k0 = kbase + 32 * j;
            const float t2a = t2_s[k0];
            const float t2b = t2_s[k0 + 1];
            #pragma unroll
            for (int i = 0; i < 8; ++i) {
                float m0 = lo32(acc[i][j]);
                float m1 = hi32(acc[i][j]);
                float d0 = __fsub_rn(__fadd_rn(t1r[i], t2a), 2.0f * m0);
                float d1 = __fsub_rn(__fadd_rn(t1r[i], t2b), 2.0f * m1);
                ull u0 = ((ull)__float_as_uint(d0) << 32) | (unsigned)k0;
                ull u1 = ((ull)__float_as_uint(d1) << 32) | (unsigned)(k0 + 1);
                if (u0 < ukey[i]) ukey[i] = u0;
                if (u1 < ukey[i]) ukey[i] = u1;
            }
        }
    }

    // ---- cross-thread argmin reduction (16 cg threads per row) ----
    #pragma unroll
    for (int i = 0; i < 8; ++i)
        red_s[(rg * 8 + i) * 16 + cg] = ukey[i];
    __syncthreads();

    if (tid < 128) {
        ull best = red_s[tid * 16];
        #pragma unroll
        for (int c = 1; c < 16; ++c) {
            ull u = red_s[tid * 16 + c];
            if (u < best) best = u;
        }
        ind_s[tid] = (int)(best & 0xffffffffu);   // smallest dist, ties -> smallest k
    }
    __syncthreads();

    // ---- gather + straight-through output + loss partial ----
    float lsum = 0.0f;
    const size_t obase = ((size_t)b << 18) + p0;
    for (int i = tid; i < 64 * 128; i += NTHREADS) {
        int d = i >> 7, r = i & 127;
        float e = e_s[d * LDE + ind_s[r]];
        float x = lo32(x2_s[(d << 7) + r]);
        float qm = __fsub_rn(e, x);                        // fl(q - lat)
        out[obase + ((size_t)d << 12) + r] = __fadd_rn(x, qm);  // fl(lat + fl(q-lat))
        lsum = fmaf(qm, qm, lsum);
    }
    // warp reduce + one double atomic per warp
    #pragma unroll
    for (int off = 16; off > 0; off >>= 1)
        lsum += __shfl_xor_sync(0xffffffffu, lsum, off);
    if ((tid & 31) == 0)
        atomicAdd(&g_loss_sum, (double)lsum);
}

__global__ void vq_fin_kernel(float* __restrict__ out, long long numel, long long loss_idx)
{
    float lm = (float)(g_loss_sum / (double)numel);
    // vq_loss = fl( fl(commitment*0.25) + embedding ), both equal lm
    out[loss_idx] = __fadd_rn(__fmul_rn(lm, 0.25f), lm);
}

extern "C" void kernel_launch(void* const* d_in, const int* in_sizes, int n_in,
                              void* d_out, int out_size)
{
    const float* lat = (const float*)d_in[0];
    const float* emb = (const float*)d_in[1];
    float* out = (float*)d_out;

    const long long numel = (long long)in_sizes[0];     // 32*64*64*64 = 8388608
    const int n_rows = (int)(numel / 64);               // 131072
    const int grid   = n_rows / TILE_M;                 // 1024

    cudaFuncSetAttribute(vq_main_kernel,
                         cudaFuncAttributeMaxDynamicSharedMemorySize, SMEM_BYTES);

    vq_zero_kernel<<<1, 1>>>();
    vq_main_kernel<<<grid, NTHREADS, SMEM_BYTES>>>(lat, emb, out);

    long long loss_idx = (out_size > numel) ? numel : (long long)out_size - 1;
    vq_fin_kernel<<<1, 1>>>(out, numel, loss_idx);
}